// round 13
// baseline (speedup 1.0000x reference)
#include <cuda_runtime.h>
#include <cuda_fp16.h>
#include <cstdint>

#define B_    16
#define C_    512
#define KA    128
#define N_    4096
#define NKEEP 51

// ---------------- scratch (device globals; no allocation allowed) --------
__device__ __half g_qh [(size_t)B_ * C_ * N_];   // 64 MiB
__device__ __half g_ql [(size_t)B_ * C_ * N_];   // 64 MiB
__device__ __half g_kh [(size_t)B_ * KA * N_];   // 16 MiB
__device__ __half g_kl [(size_t)B_ * KA * N_];   // 16 MiB
__device__ __half g_vh [(size_t)B_ * KA * N_];   // 16 MiB  [b][k][n]
__device__ __half g_vl [(size_t)B_ * KA * N_];   // 16 MiB
__device__ float  g_part[(size_t)4 * B_ * C_ * KA];  // 16 MiB split-K partials

// ---------------- helpers -------------------------------------------------
__device__ __forceinline__ uint32_t smem_u32(const void* p) {
    uint32_t a;
    asm("{ .reg .u64 t; cvta.to.shared.u64 t, %1; cvt.u32.u64 %0, t; }"
        : "=r"(a) : "l"(p));
    return a;
}

#define CP_ASYNC16(saddr, gptr) \
    asm volatile("cp.async.cg.shared.global [%0], [%1], 16;" :: "r"(saddr), "l"(gptr))
#define CP_COMMIT() asm volatile("cp.async.commit_group;" ::: "memory")
#define CP_WAIT1()  asm volatile("cp.async.wait_group 1;" ::: "memory")
#define CP_WAIT0()  asm volatile("cp.async.wait_group 0;" ::: "memory")

__device__ __forceinline__ void ldsm_x4(uint32_t (&r)[4], uint32_t addr) {
    asm volatile("ldmatrix.sync.aligned.m8n8.x4.shared.b16 {%0,%1,%2,%3}, [%4];"
                 : "=r"(r[0]), "=r"(r[1]), "=r"(r[2]), "=r"(r[3]) : "r"(addr));
}
__device__ __forceinline__ void ldsm_x4_t(uint32_t (&r)[4], uint32_t addr) {
    asm volatile("ldmatrix.sync.aligned.m8n8.x4.trans.shared.b16 {%0,%1,%2,%3}, [%4];"
                 : "=r"(r[0]), "=r"(r[1]), "=r"(r[2]), "=r"(r[3]) : "r"(addr));
}

__device__ __forceinline__ void mma16816(float (&d)[4], const uint32_t (&a)[4],
                                         uint32_t b0, uint32_t b1) {
    asm volatile(
        "mma.sync.aligned.m16n8k16.row.col.f32.f16.f16.f32 "
        "{%0,%1,%2,%3}, {%4,%5,%6,%7}, {%8,%9}, {%0,%1,%2,%3};"
        : "+f"(d[0]), "+f"(d[1]), "+f"(d[2]), "+f"(d[3])
        : "r"(a[0]), "r"(a[1]), "r"(a[2]), "r"(a[3]), "r"(b0), "r"(b1));
}

__device__ __forceinline__ void split2h(float x, __half& h, __half& l) {
    h = __float2half_rn(x);
    l = __float2half_rn(x - __half2float(h));
}

// ============================================================
// Fused depthwise 3x3 convs, 2 pixels/thread, half2 stores.
// Blocks [0, B*C) do q; [B*C, B*C+B*K) do k+v.
// ============================================================
__global__ __launch_bounds__(256) void dwconv_all_kernel(
    const float* __restrict__ xq, const float* __restrict__ xkv,
    const float* __restrict__ wq, const float* __restrict__ bq,
    const float* __restrict__ wk, const float* __restrict__ bk,
    const float* __restrict__ wv, const float* __restrict__ bv) {
    __shared__ float tile[66 * 66];
    const int blk = blockIdx.x;
    const bool isq = blk < B_ * C_;
    const int bc = isq ? blk : blk - B_ * C_;
    const int c  = isq ? (bc & (C_ - 1)) : (bc & (KA - 1));
    const float* xp = (isq ? xq : xkv) + (size_t)bc * N_;
    for (int i = threadIdx.x; i < 66 * 66; i += 256) {
        int r = i / 66 - 1, cc = i % 66 - 1;
        tile[i] = (r >= 0 && r < 64 && cc >= 0 && cc < 64) ? xp[r * 64 + cc] : 0.f;
    }
    if (isq) {
        const float w0 = wq[c*9+0], w1 = wq[c*9+1], w2 = wq[c*9+2];
        const float w3 = wq[c*9+3], w4 = wq[c*9+4], w5 = wq[c*9+5];
        const float w6 = wq[c*9+6], w7 = wq[c*9+7], w8 = wq[c*9+8];
        const float bb = bq[c];
        __syncthreads();
        __half2* yh = reinterpret_cast<__half2*>(g_qh + (size_t)bc * N_);
        __half2* yl = reinterpret_cast<__half2*>(g_ql + (size_t)bc * N_);
        for (int p2 = threadIdx.x; p2 < N_ / 2; p2 += 256) {
            int p = p2 * 2;
            int r = p >> 6, cc = p & 63;
            const float* t = tile + r * 66 + cc;
            float s0 = bb, s1 = bb;
            float a1 = t[1],  a2 = t[2];
            float b1v = t[67], b2 = t[68];
            float c1 = t[133], c2 = t[134];
            s0 = fmaf(w0, t[0],   s0); s0 = fmaf(w1, a1,  s0); s0 = fmaf(w2, a2,  s0);
            s0 = fmaf(w3, t[66],  s0); s0 = fmaf(w4, b1v, s0); s0 = fmaf(w5, b2,  s0);
            s0 = fmaf(w6, t[132], s0); s0 = fmaf(w7, c1,  s0); s0 = fmaf(w8, c2,  s0);
            s1 = fmaf(w0, a1,  s1); s1 = fmaf(w1, a2,  s1); s1 = fmaf(w2, t[3],   s1);
            s1 = fmaf(w3, b1v, s1); s1 = fmaf(w4, b2,  s1); s1 = fmaf(w5, t[69],  s1);
            s1 = fmaf(w6, c1,  s1); s1 = fmaf(w7, c2,  s1); s1 = fmaf(w8, t[135], s1);
            __half h0, l0, h1, l1;
            split2h(s0, h0, l0); split2h(s1, h1, l1);
            yh[p2] = __halves2half2(h0, h1);
            yl[p2] = __halves2half2(l0, l1);
        }
    } else {
        const float k0 = wk[c*9+0], k1 = wk[c*9+1], k2 = wk[c*9+2];
        const float k3 = wk[c*9+3], k4 = wk[c*9+4], k5 = wk[c*9+5];
        const float k6 = wk[c*9+6], k7 = wk[c*9+7], k8 = wk[c*9+8];
        const float v0 = wv[c*9+0], v1 = wv[c*9+1], v2 = wv[c*9+2];
        const float v3 = wv[c*9+3], v4 = wv[c*9+4], v5 = wv[c*9+5];
        const float v6 = wv[c*9+6], v7 = wv[c*9+7], v8 = wv[c*9+8];
        const float bbk = bk[c], bbv = bv[c];
        __syncthreads();
        __half2* kh = reinterpret_cast<__half2*>(g_kh + (size_t)bc * N_);
        __half2* kl = reinterpret_cast<__half2*>(g_kl + (size_t)bc * N_);
        __half2* vh = reinterpret_cast<__half2*>(g_vh + (size_t)bc * N_);
        __half2* vl = reinterpret_cast<__half2*>(g_vl + (size_t)bc * N_);
        for (int p2 = threadIdx.x; p2 < N_ / 2; p2 += 256) {
            int p = p2 * 2;
            int r = p >> 6, cc = p & 63;
            const float* t = tile + r * 66 + cc;
            float t0 = t[0],   a1 = t[1],  a2 = t[2],  a3 = t[3];
            float t6 = t[66],  b1v = t[67], b2 = t[68], b3 = t[69];
            float t1 = t[132], c1 = t[133], c2 = t[134], c3 = t[135];
            float sk0 = bbk, sk1 = bbk, sv0 = bbv, sv1 = bbv;
            sk0 = fmaf(k0, t0, sk0); sk0 = fmaf(k1, a1,  sk0); sk0 = fmaf(k2, a2, sk0);
            sk0 = fmaf(k3, t6, sk0); sk0 = fmaf(k4, b1v, sk0); sk0 = fmaf(k5, b2, sk0);
            sk0 = fmaf(k6, t1, sk0); sk0 = fmaf(k7, c1,  sk0); sk0 = fmaf(k8, c2, sk0);
            sk1 = fmaf(k0, a1, sk1); sk1 = fmaf(k1, a2,  sk1); sk1 = fmaf(k2, a3, sk1);
            sk1 = fmaf(k3, b1v, sk1); sk1 = fmaf(k4, b2, sk1); sk1 = fmaf(k5, b3, sk1);
            sk1 = fmaf(k6, c1, sk1); sk1 = fmaf(k7, c2,  sk1); sk1 = fmaf(k8, c3, sk1);
            sv0 = fmaf(v0, t0, sv0); sv0 = fmaf(v1, a1,  sv0); sv0 = fmaf(v2, a2, sv0);
            sv0 = fmaf(v3, t6, sv0); sv0 = fmaf(v4, b1v, sv0); sv0 = fmaf(v5, b2, sv0);
            sv0 = fmaf(v6, t1, sv0); sv0 = fmaf(v7, c1,  sv0); sv0 = fmaf(v8, c2, sv0);
            sv1 = fmaf(v0, a1, sv1); sv1 = fmaf(v1, a2,  sv1); sv1 = fmaf(v2, a3, sv1);
            sv1 = fmaf(v3, b1v, sv1); sv1 = fmaf(v4, b2, sv1); sv1 = fmaf(v5, b3, sv1);
            sv1 = fmaf(v6, c1, sv1); sv1 = fmaf(v7, c2,  sv1); sv1 = fmaf(v8, c3, sv1);
            __half h0, l0, h1, l1;
            split2h(sk0, h0, l0); split2h(sk1, h1, l1);
            kh[p2] = __halves2half2(h0, h1);
            kl[p2] = __halves2half2(l0, l1);
            split2h(sv0, h0, l0); split2h(sv1, h1, l1);
            vh[p2] = __halves2half2(h0, h1);
            vl[p2] = __halves2half2(l0, l1);
        }
    }
}

// ============================================================
// GEMM1 (split-K=4): part[ks][b][c][k] = sum_{n in ks-slice} q[c,n]*kmat[k,n]
// mma.sync fp16 3-pass. CTA tile 64x64, k-chunk 64, double-buffered cp.async.
// grid (B, mt=8, z=8: nt=z&1, ks=z>>1). 4 warps, warp tile 32x32, occ 3.
// (FROZEN — measured best rounds 5/7/9/12)
// ============================================================
#define G1_PAD  72
#define G1_ASZ  (64 * G1_PAD)
#define G1_BUFE (4 * G1_ASZ)
#define G1_SMEM (2 * G1_BUFE * 2)
#define G1_NIT  16

__global__ __launch_bounds__(128, 3) void gemm1_mma() {
    extern __shared__ __half sm1[];
    const int t = threadIdx.x, lane = t & 31, wid = t >> 5;
    const int wm = wid >> 1, wn = wid & 1;
    const int b = blockIdx.x, mt = blockIdx.y;
    const int nt = blockIdx.z & 1, ks = blockIdx.z >> 1;
    const int kbase = ks * 1024;
    const uint32_t sb = smem_u32(sm1);

    const __half* gsrc[4] = {
        g_qh + ((size_t)(b * C_ + mt * 64)) * N_,
        g_ql + ((size_t)(b * C_ + mt * 64)) * N_,
        g_kh + ((size_t)b * KA + nt * 64) * N_,
        g_kl + ((size_t)b * KA + nt * 64) * N_ };

    auto fill = [&](int bi, int n0) {
        uint32_t dbase = sb + bi * (G1_BUFE * 2);
        #pragma unroll
        for (int a = 0; a < 4; a++) {
            const __half* src = gsrc[a];
            uint32_t abase = dbase + a * (G1_ASZ * 2);
            #pragma unroll
            for (int i = 0; i < 4; i++) {
                int idx = t + 128 * i;                 // 0..511
                int row = idx >> 3, ch = (idx & 7) << 3;
                CP_ASYNC16(abase + (uint32_t)(row * G1_PAD + ch) * 2,
                           src + (size_t)row * N_ + n0 + ch);
            }
        }
    };

    fill(0, kbase);       CP_COMMIT();
    fill(1, kbase + 64);  CP_COMMIT();

    float acc[2][4][4];
    #pragma unroll
    for (int i = 0; i < 2; i++)
        #pragma unroll
        for (int j = 0; j < 4; j++)
            #pragma unroll
            for (int e = 0; e < 4; e++) acc[i][j][e] = 0.f;

    const int ar = lane & 15,                       ac = (lane >> 4) << 3;
    const int br = (lane & 7) | ((lane >> 4) << 3), bc = ((lane >> 3) & 1) << 3;

    for (int it = 0; it < G1_NIT; it++) {
        CP_WAIT1();
        __syncthreads();
        const uint32_t bufb = sb + (it & 1) * (G1_BUFE * 2);
        const uint32_t Ah = bufb, Al = bufb + G1_ASZ * 2;
        const uint32_t Bh = bufb + 2 * G1_ASZ * 2, Bl = bufb + 3 * G1_ASZ * 2;
        #pragma unroll
        for (int kk = 0; kk < 4; kk++) {
            const int k0 = kk * 16;
            uint32_t ah[2][4], al[2][4], bh[2][4], bl[2][4];
            #pragma unroll
            for (int fm = 0; fm < 2; fm++) {
                uint32_t off = (uint32_t)((wm * 32 + fm * 16 + ar) * G1_PAD + k0 + ac) * 2;
                ldsm_x4(ah[fm], Ah + off);
                ldsm_x4(al[fm], Al + off);
            }
            #pragma unroll
            for (int g = 0; g < 2; g++) {
                uint32_t off = (uint32_t)((wn * 32 + g * 16 + br) * G1_PAD + k0 + bc) * 2;
                ldsm_x4(bh[g], Bh + off);
                ldsm_x4(bl[g], Bl + off);
            }
            #pragma unroll
            for (int fm = 0; fm < 2; fm++)
                #pragma unroll
                for (int fn = 0; fn < 4; fn++) {
                    const int g = fn >> 1, p = (fn & 1) * 2;
                    mma16816(acc[fm][fn], ah[fm], bh[g][p], bh[g][p + 1]);
                    mma16816(acc[fm][fn], ah[fm], bl[g][p], bl[g][p + 1]);
                    mma16816(acc[fm][fn], al[fm], bh[g][p], bh[g][p + 1]);
                }
        }
        __syncthreads();
        if (it + 2 < G1_NIT) fill(it & 1, kbase + (it + 2) * 64);
        CP_COMMIT();
    }
    CP_WAIT0();

    float* base = g_part + ((size_t)(ks * B_ + b) * C_) * KA;
    #pragma unroll
    for (int fm = 0; fm < 2; fm++) {
        int r0 = mt * 64 + wm * 32 + fm * 16 + (lane >> 2);
        #pragma unroll
        for (int fn = 0; fn < 4; fn++) {
            int cc = nt * 64 + wn * 32 + fn * 8 + (lane & 3) * 2;
            float* d0 = base + (size_t)r0 * KA + cc;
            d0[0] = acc[fm][fn][0];
            d0[1] = acc[fm][fn][1];
            float* d1 = d0 + 8 * KA;
            d1[0] = acc[fm][fn][2];
            d1[1] = acc[fm][fn][3];
        }
    }
}

// ============================================================
// Split-K reduce + scale + softmax. 4 rows per 512-thread block.
// ============================================================
__global__ __launch_bounds__(512) void reduce_softmax_kernel(float* __restrict__ AW) {
    const int t   = threadIdx.x;
    const int g   = t >> 7;              // row group 0..3
    const int tid = t & 127;             // lane within row
    const int bc  = blockIdx.x * 4 + g;
    float v = 0.f;
    #pragma unroll
    for (int ps = 0; ps < 4; ps++)
        v += g_part[((size_t)ps * B_ * C_ + bc) * KA + tid];
    v *= 0.0883883476483184f;            // 1/sqrt(128)
    __shared__ float red[4][4];
    float m = v;
    #pragma unroll
    for (int o = 16; o; o >>= 1) m = fmaxf(m, __shfl_xor_sync(0xffffffffu, m, o));
    if ((tid & 31) == 0) red[g][(tid >> 5)] = m;
    __syncthreads();
    m = fmaxf(fmaxf(red[g][0], red[g][1]), fmaxf(red[g][2], red[g][3]));
    float e = expf(v - m);
    float s = e;
    #pragma unroll
    for (int o = 16; o; o >>= 1) s += __shfl_xor_sync(0xffffffffu, s, o);
    __syncthreads();
    if ((tid & 31) == 0) red[g][(tid >> 5)] = s;
    __syncthreads();
    s = red[g][0] + red[g][1] + red[g][2] + red[g][3];
    AW[(size_t)bc * KA + tid] = e / s;
}

// ============================================================
// Top-51-of-512 mask v3: coalesced smem staging + warp-per-column select.
// 256 blocks x 256 threads. Block (b, kg): slab aw[b][0:512][kg*8:+8]
// loaded coalesced (32B/row sectors) into smem [512][9] (9 coprime 32 ->
// conflict-free column reads). 8 warps each select 1 column via lane-local
// counts + 5-shfl reduce, per-warp early exit. Coalesced write-back.
// Selection arithmetic identical to prior rounds.
// ============================================================
__global__ __launch_bounds__(256) void topk_mask_kernel(float* __restrict__ AW) {
    __shared__ float s[512 * 9];
    const int b  = blockIdx.x >> 4;
    const int kg = (blockIdx.x & 15) * 8;
    const int t  = threadIdx.x;
    const int wid = t >> 5, lane = t & 31;

    #pragma unroll
    for (int i = 0; i < 16; i++) {
        int idx = t + 256 * i;             // 0..4095
        int c = idx >> 3, j = idx & 7;
        s[c * 9 + j] = AW[((size_t)(b * C_ + c)) * KA + kg + j];
    }
    __syncthreads();

    {
        const int j = wid;                 // 1 column per warp
        unsigned u[16];
        #pragma unroll
        for (int i = 0; i < 16; i++) {
            unsigned x = __float_as_uint(s[(lane + 32 * i) * 9 + j]);
            u[i] = (x & 0x80000000u) ? ~x : (x | 0x80000000u);
        }
        unsigned thr = 0x80000000u;
        for (int bit = 29; bit >= 0; bit--) {
            unsigned cand = thr | (1u << bit);
            int cnt = 0;
            #pragma unroll
            for (int i = 0; i < 16; i++) cnt += (u[i] >= cand);
            #pragma unroll
            for (int o = 16; o; o >>= 1) cnt += __shfl_xor_sync(0xffffffffu, cnt, o);
            if (cnt >= NKEEP) {
                thr = cand;
                if (cnt == NKEEP) break;   // warp-uniform early exit
            }
        }
        #pragma unroll
        for (int i = 0; i < 16; i++)
            if (u[i] < thr) s[(lane + 32 * i) * 9 + j] = 0.f;
    }
    __syncthreads();

    #pragma unroll
    for (int i = 0; i < 16; i++) {
        int idx = t + 256 * i;
        int c = idx >> 3, j = idx & 7;
        AW[((size_t)(b * C_ + c)) * KA + kg + j] = s[c * 9 + j];
    }
}

// ============================================================
// GEMM2 (2-pass): out[b,c,n] = x_q[b,c,n] + sum_k aw[c,k]*v[k,n]
// aw -> fp16 (single), v hi/lo. Passes: ah*bh + ah*bl.
// CTA 64(m) x 128(n), K=128 single shot, B via cp.async + ldmatrix.trans.
// 8 warps (2m x 4n), warp tile 32x32. grid (B, 8, 32). smem 87KB -> 2 CTA/SM.
// (FROZEN — measured best rounds 7/9/12)
// ============================================================
#define G2_PAD   136
#define G2_A_E   (64 * G2_PAD)
#define G2_B_E   (128 * G2_PAD)
#define G2_SMEM  ((G2_A_E + 2 * G2_B_E) * 2)

__global__ __launch_bounds__(256, 2) void gemm2_mma(
    const float* __restrict__ AW, const float* __restrict__ XQ,
    float* __restrict__ OUT) {
    extern __shared__ __half sm2[];
    __half* Ah = sm2;
    const int t = threadIdx.x, lane = t & 31, wid = t >> 5;
    const int wm = wid >> 2, wn = wid & 3;
    const int b = blockIdx.x, mt = blockIdx.y, nt = blockIdx.z;
    const uint32_t sb = smem_u32(sm2);

    // B: cp.async v hi/lo tiles [k=128][n=128] (natural layout)
    {
        const __half* sh = g_vh + (size_t)b * KA * N_ + nt * 128;
        const __half* sl = g_vl + (size_t)b * KA * N_ + nt * 128;
        const uint32_t bh0 = sb + G2_A_E * 2, bl0 = bh0 + G2_B_E * 2;
        #pragma unroll
        for (int i = 0; i < 8; i++) {
            int idx = t + 256 * i;                 // 0..2047
            int row = idx >> 4, ch = (idx & 15) << 3;
            uint32_t doff = (uint32_t)(row * G2_PAD + ch) * 2;
            CP_ASYNC16(bh0 + doff, sh + (size_t)row * N_ + ch);
            CP_ASYNC16(bl0 + doff, sl + (size_t)row * N_ + ch);
        }
        CP_COMMIT();
    }
    // A: convert aw (fp32, post-mask) to fp16 (overlaps B cp.async)
    {
        const float* asrc = AW + ((size_t)(b * C_ + mt * 64)) * KA;
        #pragma unroll
        for (int i = 0; i < 8; i++) {
            int idx = t + 256 * i;                 // 0..2047
            int row = idx >> 5, c4 = (idx & 31) << 2;
            float4 v = *reinterpret_cast<const float4*>(asrc + (size_t)row * KA + c4);
            __half* dh = Ah + row * G2_PAD + c4;
            dh[0] = __float2half_rn(v.x);
            dh[1] = __float2half_rn(v.y);
            dh[2] = __float2half_rn(v.z);
            dh[3] = __float2half_rn(v.w);
        }
    }
    CP_WAIT0();
    __syncthreads();

    float acc[2][4][4];
    #pragma unroll
    for (int i = 0; i < 2; i++)
        #pragma unroll
        for (int j = 0; j < 4; j++)
            #pragma unroll
            for (int e = 0; e < 4; e++) acc[i][j][e] = 0.f;

    const uint32_t oAh = 0;
    const uint32_t oBh = G2_A_E * 2, oBl = oBh + G2_B_E * 2;
    const int ar = lane & 15, axc = (lane >> 4) << 3;

    #pragma unroll
    for (int kk = 0; kk < 8; kk++) {
        const int k0 = kk * 16;
        uint32_t ah[2][4], bh[2][4], bl[2][4];
        #pragma unroll
        for (int fm = 0; fm < 2; fm++) {
            uint32_t off = (uint32_t)((wm * 32 + fm * 16 + ar) * G2_PAD + k0 + axc) * 2;
            ldsm_x4(ah[fm], sb + oAh + off);
        }
        #pragma unroll
        for (int g = 0; g < 2; g++) {
            uint32_t off = (uint32_t)((k0 + ar) * G2_PAD + wn * 32 + g * 16 + axc) * 2;
            ldsm_x4_t(bh[g], sb + oBh + off);
            ldsm_x4_t(bl[g], sb + oBl + off);
        }
        #pragma unroll
        for (int fm = 0; fm < 2; fm++)
            #pragma unroll
            for (int fn = 0; fn < 4; fn++) {
                const int g = fn >> 1, p = (fn & 1) * 2;
                mma16816(acc[fm][fn], ah[fm], bh[g][p], bh[g][p + 1]);
                mma16816(acc[fm][fn], ah[fm], bl[g][p], bl[g][p + 1]);
            }
    }

    #pragma unroll
    for (int fm = 0; fm < 2; fm++) {
        int r0 = mt * 64 + wm * 32 + fm * 16 + (lane >> 2);
        #pragma unroll
        for (int fn = 0; fn < 4; fn++) {
            int cc = nt * 128 + wn * 32 + fn * 8 + (lane & 3) * 2;
            size_t off0 = ((size_t)(b * C_ + r0)) * N_ + cc;
            float2 x0 = *reinterpret_cast<const float2*>(XQ + off0);
            float2 o0 = make_float2(x0.x + acc[fm][fn][0], x0.y + acc[fm][fn][1]);
            *reinterpret_cast<float2*>(OUT + off0) = o0;
            size_t off1 = off0 + (size_t)8 * N_;
            float2 x1 = *reinterpret_cast<const float2*>(XQ + off1);
            float2 o1 = make_float2(x1.x + acc[fm][fn][2], x1.y + acc[fm][fn][3]);
            *reinterpret_cast<float2*>(OUT + off1) = o1;
        }
    }
}

// ============================================================
extern "C" void kernel_launch(void* const* d_in, const int* in_sizes, int n_in,
                              void* d_out, int out_size) {
    const float* x_q  = (const float*)d_in[0];
    const float* x_kv = (const float*)d_in[1];
    const float* wq   = (const float*)d_in[2];
    const float* bq   = (const float*)d_in[3];
    const float* wk   = (const float*)d_in[4];
    const float* bk   = (const float*)d_in[5];
    const float* wv   = (const float*)d_in[6];
    const float* bv   = (const float*)d_in[7];

    float* out1 = (float*)d_out;                   // [B,C,H,W]
    float* aw   = out1 + (size_t)B_ * C_ * N_;     // [B,C,K]

    static int configured = 0;
    if (!configured) {
        cudaFuncSetAttribute(gemm1_mma,
                             cudaFuncAttributeMaxDynamicSharedMemorySize, G1_SMEM);
        cudaFuncSetAttribute(gemm2_mma,
                             cudaFuncAttributeMaxDynamicSharedMemorySize, G2_SMEM);
        configured = 1;
    }

    dwconv_all_kernel    <<<B_ * C_ + B_ * KA, 256>>>(x_q, x_kv, wq, bq, wk, bk, wv, bv);
    gemm1_mma            <<<dim3(B_, 8, 8), 128, G1_SMEM>>>();
    reduce_softmax_kernel<<<B_ * C_ / 4, 512>>>(aw);
    topk_mask_kernel     <<<B_ * 16, 256>>>(aw);
    gemm2_mma            <<<dim3(B_, 8, 32), 256, G2_SMEM>>>(aw, x_q, out1);
}

// round 14
// speedup vs baseline: 1.0312x; 1.0312x over previous
#include <cuda_runtime.h>
#include <cuda_fp16.h>
#include <cstdint>

#define B_    16
#define C_    512
#define KA    128
#define N_    4096
#define NKEEP 51

// ---------------- scratch (device globals; no allocation allowed) --------
__device__ __half g_qh [(size_t)B_ * C_ * N_];   // 64 MiB
__device__ __half g_ql [(size_t)B_ * C_ * N_];   // 64 MiB
__device__ __half g_kh [(size_t)B_ * KA * N_];   // 16 MiB
__device__ __half g_kl [(size_t)B_ * KA * N_];   // 16 MiB
__device__ __half g_vh [(size_t)B_ * KA * N_];   // 16 MiB  [b][k][n]
__device__ __half g_vl [(size_t)B_ * KA * N_];   // 16 MiB
__device__ float  g_part[(size_t)4 * B_ * C_ * KA];  // 16 MiB split-K partials

// ---------------- helpers -------------------------------------------------
__device__ __forceinline__ uint32_t smem_u32(const void* p) {
    uint32_t a;
    asm("{ .reg .u64 t; cvta.to.shared.u64 t, %1; cvt.u32.u64 %0, t; }"
        : "=r"(a) : "l"(p));
    return a;
}

#define CP_ASYNC16(saddr, gptr) \
    asm volatile("cp.async.cg.shared.global [%0], [%1], 16;" :: "r"(saddr), "l"(gptr))
#define CP_COMMIT() asm volatile("cp.async.commit_group;" ::: "memory")
#define CP_WAIT1()  asm volatile("cp.async.wait_group 1;" ::: "memory")
#define CP_WAIT0()  asm volatile("cp.async.wait_group 0;" ::: "memory")

__device__ __forceinline__ void ldsm_x4(uint32_t (&r)[4], uint32_t addr) {
    asm volatile("ldmatrix.sync.aligned.m8n8.x4.shared.b16 {%0,%1,%2,%3}, [%4];"
                 : "=r"(r[0]), "=r"(r[1]), "=r"(r[2]), "=r"(r[3]) : "r"(addr));
}
__device__ __forceinline__ void ldsm_x4_t(uint32_t (&r)[4], uint32_t addr) {
    asm volatile("ldmatrix.sync.aligned.m8n8.x4.trans.shared.b16 {%0,%1,%2,%3}, [%4];"
                 : "=r"(r[0]), "=r"(r[1]), "=r"(r[2]), "=r"(r[3]) : "r"(addr));
}

__device__ __forceinline__ void mma16816(float (&d)[4], const uint32_t (&a)[4],
                                         uint32_t b0, uint32_t b1) {
    asm volatile(
        "mma.sync.aligned.m16n8k16.row.col.f32.f16.f16.f32 "
        "{%0,%1,%2,%3}, {%4,%5,%6,%7}, {%8,%9}, {%0,%1,%2,%3};"
        : "+f"(d[0]), "+f"(d[1]), "+f"(d[2]), "+f"(d[3])
        : "r"(a[0]), "r"(a[1]), "r"(a[2]), "r"(a[3]), "r"(b0), "r"(b1));
}

__device__ __forceinline__ void split2h(float x, __half& h, __half& l) {
    h = __float2half_rn(x);
    l = __float2half_rn(x - __half2float(h));
}

// ============================================================
// Fused depthwise 3x3 convs (round-12 version — 1 pixel/thread).
// Blocks [0, B*C) do q; [B*C, B*C+B*K) do k+v.
// ============================================================
__global__ __launch_bounds__(256) void dwconv_all_kernel(
    const float* __restrict__ xq, const float* __restrict__ xkv,
    const float* __restrict__ wq, const float* __restrict__ bq,
    const float* __restrict__ wk, const float* __restrict__ bk,
    const float* __restrict__ wv, const float* __restrict__ bv) {
    __shared__ float tile[66 * 66];
    const int blk = blockIdx.x;
    const bool isq = blk < B_ * C_;
    const int bc = isq ? blk : blk - B_ * C_;
    const int c  = isq ? (bc & (C_ - 1)) : (bc & (KA - 1));
    const float* xp = (isq ? xq : xkv) + (size_t)bc * N_;
    for (int i = threadIdx.x; i < 66 * 66; i += 256) {
        int r = i / 66 - 1, cc = i % 66 - 1;
        tile[i] = (r >= 0 && r < 64 && cc >= 0 && cc < 64) ? xp[r * 64 + cc] : 0.f;
    }
    if (isq) {
        const float w0 = wq[c*9+0], w1 = wq[c*9+1], w2 = wq[c*9+2];
        const float w3 = wq[c*9+3], w4 = wq[c*9+4], w5 = wq[c*9+5];
        const float w6 = wq[c*9+6], w7 = wq[c*9+7], w8 = wq[c*9+8];
        const float bb = bq[c];
        __syncthreads();
        __half* yh = g_qh + (size_t)bc * N_;
        __half* yl = g_ql + (size_t)bc * N_;
        for (int p = threadIdx.x; p < N_; p += 256) {
            int r = p >> 6, cc = p & 63;
            const float* t = tile + r * 66 + cc;
            float s = bb;
            s = fmaf(w0, t[0],   s); s = fmaf(w1, t[1],   s); s = fmaf(w2, t[2],   s);
            s = fmaf(w3, t[66],  s); s = fmaf(w4, t[67],  s); s = fmaf(w5, t[68],  s);
            s = fmaf(w6, t[132], s); s = fmaf(w7, t[133], s); s = fmaf(w8, t[134], s);
            __half h, l; split2h(s, h, l);
            yh[p] = h; yl[p] = l;
        }
    } else {
        const float k0 = wk[c*9+0], k1 = wk[c*9+1], k2 = wk[c*9+2];
        const float k3 = wk[c*9+3], k4 = wk[c*9+4], k5 = wk[c*9+5];
        const float k6 = wk[c*9+6], k7 = wk[c*9+7], k8 = wk[c*9+8];
        const float v0 = wv[c*9+0], v1 = wv[c*9+1], v2 = wv[c*9+2];
        const float v3 = wv[c*9+3], v4 = wv[c*9+4], v5 = wv[c*9+5];
        const float v6 = wv[c*9+6], v7 = wv[c*9+7], v8 = wv[c*9+8];
        const float bbk = bk[c], bbv = bv[c];
        __syncthreads();
        __half* kh = g_kh + (size_t)bc * N_;
        __half* kl = g_kl + (size_t)bc * N_;
        __half* vh = g_vh + (size_t)bc * N_;
        __half* vl = g_vl + (size_t)bc * N_;
        for (int p = threadIdx.x; p < N_; p += 256) {
            int r = p >> 6, cc = p & 63;
            const float* t = tile + r * 66 + cc;
            float sk = bbk, sv = bbv;
            sk = fmaf(k0, t[0],   sk); sk = fmaf(k1, t[1],   sk); sk = fmaf(k2, t[2],   sk);
            sk = fmaf(k3, t[66],  sk); sk = fmaf(k4, t[67],  sk); sk = fmaf(k5, t[68],  sk);
            sk = fmaf(k6, t[132], sk); sk = fmaf(k7, t[133], sk); sk = fmaf(k8, t[134], sk);
            sv = fmaf(v0, t[0],   sv); sv = fmaf(v1, t[1],   sv); sv = fmaf(v2, t[2],   sv);
            sv = fmaf(v3, t[66],  sv); sv = fmaf(v4, t[67],  sv); sv = fmaf(v5, t[68],  sv);
            sv = fmaf(v6, t[132], sv); sv = fmaf(v7, t[133], sv); sv = fmaf(v8, t[134], sv);
            __half h, l;
            split2h(sk, h, l); kh[p] = h; kl[p] = l;
            split2h(sv, h, l); vh[p] = h; vl[p] = l;
        }
    }
}

// ============================================================
// GEMM1 (split-K=4): part[ks][b][c][k] = sum_{n in ks-slice} q[c,n]*kmat[k,n]
// mma.sync fp16 3-pass. CTA tile 64x64, k-chunk 64, double-buffered cp.async.
// grid (B, mt=8, z=8: nt=z&1, ks=z>>1). 4 warps, warp tile 32x32, occ 3.
// (FROZEN — measured best rounds 5/7/9/12)
// ============================================================
#define G1_PAD  72
#define G1_ASZ  (64 * G1_PAD)
#define G1_BUFE (4 * G1_ASZ)
#define G1_SMEM (2 * G1_BUFE * 2)
#define G1_NIT  16

__global__ __launch_bounds__(128, 3) void gemm1_mma() {
    extern __shared__ __half sm1[];
    const int t = threadIdx.x, lane = t & 31, wid = t >> 5;
    const int wm = wid >> 1, wn = wid & 1;
    const int b = blockIdx.x, mt = blockIdx.y;
    const int nt = blockIdx.z & 1, ks = blockIdx.z >> 1;
    const int kbase = ks * 1024;
    const uint32_t sb = smem_u32(sm1);

    const __half* gsrc[4] = {
        g_qh + ((size_t)(b * C_ + mt * 64)) * N_,
        g_ql + ((size_t)(b * C_ + mt * 64)) * N_,
        g_kh + ((size_t)b * KA + nt * 64) * N_,
        g_kl + ((size_t)b * KA + nt * 64) * N_ };

    auto fill = [&](int bi, int n0) {
        uint32_t dbase = sb + bi * (G1_BUFE * 2);
        #pragma unroll
        for (int a = 0; a < 4; a++) {
            const __half* src = gsrc[a];
            uint32_t abase = dbase + a * (G1_ASZ * 2);
            #pragma unroll
            for (int i = 0; i < 4; i++) {
                int idx = t + 128 * i;                 // 0..511
                int row = idx >> 3, ch = (idx & 7) << 3;
                CP_ASYNC16(abase + (uint32_t)(row * G1_PAD + ch) * 2,
                           src + (size_t)row * N_ + n0 + ch);
            }
        }
    };

    fill(0, kbase);       CP_COMMIT();
    fill(1, kbase + 64);  CP_COMMIT();

    float acc[2][4][4];
    #pragma unroll
    for (int i = 0; i < 2; i++)
        #pragma unroll
        for (int j = 0; j < 4; j++)
            #pragma unroll
            for (int e = 0; e < 4; e++) acc[i][j][e] = 0.f;

    const int ar = lane & 15,                       ac = (lane >> 4) << 3;
    const int br = (lane & 7) | ((lane >> 4) << 3), bc = ((lane >> 3) & 1) << 3;

    for (int it = 0; it < G1_NIT; it++) {
        CP_WAIT1();
        __syncthreads();
        const uint32_t bufb = sb + (it & 1) * (G1_BUFE * 2);
        const uint32_t Ah = bufb, Al = bufb + G1_ASZ * 2;
        const uint32_t Bh = bufb + 2 * G1_ASZ * 2, Bl = bufb + 3 * G1_ASZ * 2;
        #pragma unroll
        for (int kk = 0; kk < 4; kk++) {
            const int k0 = kk * 16;
            uint32_t ah[2][4], al[2][4], bh[2][4], bl[2][4];
            #pragma unroll
            for (int fm = 0; fm < 2; fm++) {
                uint32_t off = (uint32_t)((wm * 32 + fm * 16 + ar) * G1_PAD + k0 + ac) * 2;
                ldsm_x4(ah[fm], Ah + off);
                ldsm_x4(al[fm], Al + off);
            }
            #pragma unroll
            for (int g = 0; g < 2; g++) {
                uint32_t off = (uint32_t)((wn * 32 + g * 16 + br) * G1_PAD + k0 + bc) * 2;
                ldsm_x4(bh[g], Bh + off);
                ldsm_x4(bl[g], Bl + off);
            }
            #pragma unroll
            for (int fm = 0; fm < 2; fm++)
                #pragma unroll
                for (int fn = 0; fn < 4; fn++) {
                    const int g = fn >> 1, p = (fn & 1) * 2;
                    mma16816(acc[fm][fn], ah[fm], bh[g][p], bh[g][p + 1]);
                    mma16816(acc[fm][fn], ah[fm], bl[g][p], bl[g][p + 1]);
                    mma16816(acc[fm][fn], al[fm], bh[g][p], bh[g][p + 1]);
                }
        }
        __syncthreads();
        if (it + 2 < G1_NIT) fill(it & 1, kbase + (it + 2) * 64);
        CP_COMMIT();
    }
    CP_WAIT0();

    float* base = g_part + ((size_t)(ks * B_ + b) * C_) * KA;
    #pragma unroll
    for (int fm = 0; fm < 2; fm++) {
        int r0 = mt * 64 + wm * 32 + fm * 16 + (lane >> 2);
        #pragma unroll
        for (int fn = 0; fn < 4; fn++) {
            int cc = nt * 64 + wn * 32 + fn * 8 + (lane & 3) * 2;
            float* d0 = base + (size_t)r0 * KA + cc;
            d0[0] = acc[fm][fn][0];
            d0[1] = acc[fm][fn][1];
            float* d1 = d0 + 8 * KA;
            d1[0] = acc[fm][fn][2];
            d1[1] = acc[fm][fn][3];
        }
    }
}

// ============================================================
// Split-K reduce + scale + softmax. 4 rows per 512-thread block.
// ============================================================
__global__ __launch_bounds__(512) void reduce_softmax_kernel(float* __restrict__ AW) {
    const int t   = threadIdx.x;
    const int g   = t >> 7;              // row group 0..3
    const int tid = t & 127;             // lane within row
    const int bc  = blockIdx.x * 4 + g;
    float v = 0.f;
    #pragma unroll
    for (int ps = 0; ps < 4; ps++)
        v += g_part[((size_t)ps * B_ * C_ + bc) * KA + tid];
    v *= 0.0883883476483184f;            // 1/sqrt(128)
    __shared__ float red[4][4];
    float m = v;
    #pragma unroll
    for (int o = 16; o; o >>= 1) m = fmaxf(m, __shfl_xor_sync(0xffffffffu, m, o));
    if ((tid & 31) == 0) red[g][(tid >> 5)] = m;
    __syncthreads();
    m = fmaxf(fmaxf(red[g][0], red[g][1]), fmaxf(red[g][2], red[g][3]));
    float e = expf(v - m);
    float s = e;
    #pragma unroll
    for (int o = 16; o; o >>= 1) s += __shfl_xor_sync(0xffffffffu, s, o);
    __syncthreads();
    if ((tid & 31) == 0) red[g][(tid >> 5)] = s;
    __syncthreads();
    s = red[g][0] + red[g][1] + red[g][2] + red[g][3];
    AW[(size_t)bc * KA + tid] = e / s;
}

// ============================================================
// Top-51-of-512 mask v3: coalesced smem staging + warp-per-column select.
// (round-13 measured version: 14.0 -> 10.4 us)
// ============================================================
__global__ __launch_bounds__(256) void topk_mask_kernel(float* __restrict__ AW) {
    __shared__ float s[512 * 9];
    const int b  = blockIdx.x >> 4;
    const int kg = (blockIdx.x & 15) * 8;
    const int t  = threadIdx.x;
    const int wid = t >> 5, lane = t & 31;

    #pragma unroll
    for (int i = 0; i < 16; i++) {
        int idx = t + 256 * i;             // 0..4095
        int c = idx >> 3, j = idx & 7;
        s[c * 9 + j] = AW[((size_t)(b * C_ + c)) * KA + kg + j];
    }
    __syncthreads();

    {
        const int j = wid;                 // 1 column per warp
        unsigned u[16];
        #pragma unroll
        for (int i = 0; i < 16; i++) {
            unsigned x = __float_as_uint(s[(lane + 32 * i) * 9 + j]);
            u[i] = (x & 0x80000000u) ? ~x : (x | 0x80000000u);
        }
        unsigned thr = 0x80000000u;
        for (int bit = 29; bit >= 0; bit--) {
            unsigned cand = thr | (1u << bit);
            int cnt = 0;
            #pragma unroll
            for (int i = 0; i < 16; i++) cnt += (u[i] >= cand);
            #pragma unroll
            for (int o = 16; o; o >>= 1) cnt += __shfl_xor_sync(0xffffffffu, cnt, o);
            if (cnt >= NKEEP) {
                thr = cand;
                if (cnt == NKEEP) break;   // warp-uniform early exit
            }
        }
        #pragma unroll
        for (int i = 0; i < 16; i++)
            if (u[i] < thr) s[(lane + 32 * i) * 9 + j] = 0.f;
    }
    __syncthreads();

    #pragma unroll
    for (int i = 0; i < 16; i++) {
        int idx = t + 256 * i;
        int c = idx >> 3, j = idx & 7;
        AW[((size_t)(b * C_ + c)) * KA + kg + j] = s[c * 9 + j];
    }
}

// ============================================================
// GEMM2 (2-pass): out[b,c,n] = x_q[b,c,n] + sum_k aw[c,k]*v[k,n]
// aw -> fp16 (single), v hi/lo. Passes: ah*bh + ah*bl.
// CTA 64(m) x 128(n), K=128 single shot, B via cp.async + ldmatrix.trans.
// 8 warps (2m x 4n), warp tile 32x32. grid (B, 8, 32). smem 87KB -> 2 CTA/SM.
// (FROZEN — measured best rounds 7/9/12)
// ============================================================
#define G2_PAD   136
#define G2_A_E   (64 * G2_PAD)
#define G2_B_E   (128 * G2_PAD)
#define G2_SMEM  ((G2_A_E + 2 * G2_B_E) * 2)

__global__ __launch_bounds__(256, 2) void gemm2_mma(
    const float* __restrict__ AW, const float* __restrict__ XQ,
    float* __restrict__ OUT) {
    extern __shared__ __half sm2[];
    __half* Ah = sm2;
    const int t = threadIdx.x, lane = t & 31, wid = t >> 5;
    const int wm = wid >> 2, wn = wid & 3;
    const int b = blockIdx.x, mt = blockIdx.y, nt = blockIdx.z;
    const uint32_t sb = smem_u32(sm2);

    // B: cp.async v hi/lo tiles [k=128][n=128] (natural layout)
    {
        const __half* sh = g_vh + (size_t)b * KA * N_ + nt * 128;
        const __half* sl = g_vl + (size_t)b * KA * N_ + nt * 128;
        const uint32_t bh0 = sb + G2_A_E * 2, bl0 = bh0 + G2_B_E * 2;
        #pragma unroll
        for (int i = 0; i < 8; i++) {
            int idx = t + 256 * i;                 // 0..2047
            int row = idx >> 4, ch = (idx & 15) << 3;
            uint32_t doff = (uint32_t)(row * G2_PAD + ch) * 2;
            CP_ASYNC16(bh0 + doff, sh + (size_t)row * N_ + ch);
            CP_ASYNC16(bl0 + doff, sl + (size_t)row * N_ + ch);
        }
        CP_COMMIT();
    }
    // A: convert aw (fp32, post-mask) to fp16 (overlaps B cp.async)
    {
        const float* asrc = AW + ((size_t)(b * C_ + mt * 64)) * KA;
        #pragma unroll
        for (int i = 0; i < 8; i++) {
            int idx = t + 256 * i;                 // 0..2047
            int row = idx >> 5, c4 = (idx & 31) << 2;
            float4 v = *reinterpret_cast<const float4*>(asrc + (size_t)row * KA + c4);
            __half* dh = Ah + row * G2_PAD + c4;
            dh[0] = __float2half_rn(v.x);
            dh[1] = __float2half_rn(v.y);
            dh[2] = __float2half_rn(v.z);
            dh[3] = __float2half_rn(v.w);
        }
    }
    CP_WAIT0();
    __syncthreads();

    float acc[2][4][4];
    #pragma unroll
    for (int i = 0; i < 2; i++)
        #pragma unroll
        for (int j = 0; j < 4; j++)
            #pragma unroll
            for (int e = 0; e < 4; e++) acc[i][j][e] = 0.f;

    const uint32_t oAh = 0;
    const uint32_t oBh = G2_A_E * 2, oBl = oBh + G2_B_E * 2;
    const int ar = lane & 15, axc = (lane >> 4) << 3;

    #pragma unroll
    for (int kk = 0; kk < 8; kk++) {
        const int k0 = kk * 16;
        uint32_t ah[2][4], bh[2][4], bl[2][4];
        #pragma unroll
        for (int fm = 0; fm < 2; fm++) {
            uint32_t off = (uint32_t)((wm * 32 + fm * 16 + ar) * G2_PAD + k0 + axc) * 2;
            ldsm_x4(ah[fm], sb + oAh + off);
        }
        #pragma unroll
        for (int g = 0; g < 2; g++) {
            uint32_t off = (uint32_t)((k0 + ar) * G2_PAD + wn * 32 + g * 16 + axc) * 2;
            ldsm_x4_t(bh[g], sb + oBh + off);
            ldsm_x4_t(bl[g], sb + oBl + off);
        }
        #pragma unroll
        for (int fm = 0; fm < 2; fm++)
            #pragma unroll
            for (int fn = 0; fn < 4; fn++) {
                const int g = fn >> 1, p = (fn & 1) * 2;
                mma16816(acc[fm][fn], ah[fm], bh[g][p], bh[g][p + 1]);
                mma16816(acc[fm][fn], ah[fm], bl[g][p], bl[g][p + 1]);
            }
    }

    #pragma unroll
    for (int fm = 0; fm < 2; fm++) {
        int r0 = mt * 64 + wm * 32 + fm * 16 + (lane >> 2);
        #pragma unroll
        for (int fn = 0; fn < 4; fn++) {
            int cc = nt * 128 + wn * 32 + fn * 8 + (lane & 3) * 2;
            size_t off0 = ((size_t)(b * C_ + r0)) * N_ + cc;
            float2 x0 = *reinterpret_cast<const float2*>(XQ + off0);
            float2 o0 = make_float2(x0.x + acc[fm][fn][0], x0.y + acc[fm][fn][1]);
            *reinterpret_cast<float2*>(OUT + off0) = o0;
            size_t off1 = off0 + (size_t)8 * N_;
            float2 x1 = *reinterpret_cast<const float2*>(XQ + off1);
            float2 o1 = make_float2(x1.x + acc[fm][fn][2], x1.y + acc[fm][fn][3]);
            *reinterpret_cast<float2*>(OUT + off1) = o1;
        }
    }
}

// ============================================================
extern "C" void kernel_launch(void* const* d_in, const int* in_sizes, int n_in,
                              void* d_out, int out_size) {
    const float* x_q  = (const float*)d_in[0];
    const float* x_kv = (const float*)d_in[1];
    const float* wq   = (const float*)d_in[2];
    const float* bq   = (const float*)d_in[3];
    const float* wk   = (const float*)d_in[4];
    const float* bk   = (const float*)d_in[5];
    const float* wv   = (const float*)d_in[6];
    const float* bv   = (const float*)d_in[7];

    float* out1 = (float*)d_out;                   // [B,C,H,W]
    float* aw   = out1 + (size_t)B_ * C_ * N_;     // [B,C,K]

    static int configured = 0;
    if (!configured) {
        cudaFuncSetAttribute(gemm1_mma,
                             cudaFuncAttributeMaxDynamicSharedMemorySize, G1_SMEM);
        cudaFuncSetAttribute(gemm2_mma,
                             cudaFuncAttributeMaxDynamicSharedMemorySize, G2_SMEM);
        configured = 1;
    }

    dwconv_all_kernel    <<<B_ * C_ + B_ * KA, 256>>>(x_q, x_kv, wq, bq, wk, bk, wv, bv);
    gemm1_mma            <<<dim3(B_, 8, 8), 128, G1_SMEM>>>();
    reduce_softmax_kernel<<<B_ * C_ / 4, 512>>>(aw);
    topk_mask_kernel     <<<B_ * 16, 256>>>(aw);
    gemm2_mma            <<<dim3(B_, 8, 32), 256, G2_SMEM>>>(aw, x_q, out1);
}

// round 15
// speedup vs baseline: 1.0760x; 1.0435x over previous
#include <cuda_runtime.h>
#include <cuda_fp16.h>
#include <cstdint>

#define B_    16
#define C_    512
#define KA    128
#define N_    4096
#define NKEEP 51

// ---------------- scratch (device globals; no allocation allowed) --------
__device__ __half g_qh [(size_t)B_ * C_ * N_];   // 64 MiB
__device__ __half g_ql [(size_t)B_ * C_ * N_];   // 64 MiB
__device__ __half g_kh [(size_t)B_ * KA * N_];   // 16 MiB
__device__ __half g_kl [(size_t)B_ * KA * N_];   // 16 MiB
__device__ __half g_vh [(size_t)B_ * KA * N_];   // 16 MiB  [b][k][n]
__device__ float  g_part[(size_t)4 * B_ * C_ * KA];  // 16 MiB split-K partials

// ---------------- helpers -------------------------------------------------
__device__ __forceinline__ uint32_t smem_u32(const void* p) {
    uint32_t a;
    asm("{ .reg .u64 t; cvta.to.shared.u64 t, %1; cvt.u32.u64 %0, t; }"
        : "=r"(a) : "l"(p));
    return a;
}

#define CP_ASYNC16(saddr, gptr) \
    asm volatile("cp.async.cg.shared.global [%0], [%1], 16;" :: "r"(saddr), "l"(gptr))
#define CP_COMMIT() asm volatile("cp.async.commit_group;" ::: "memory")
#define CP_WAIT1()  asm volatile("cp.async.wait_group 1;" ::: "memory")
#define CP_WAIT0()  asm volatile("cp.async.wait_group 0;" ::: "memory")

__device__ __forceinline__ void ldsm_x4(uint32_t (&r)[4], uint32_t addr) {
    asm volatile("ldmatrix.sync.aligned.m8n8.x4.shared.b16 {%0,%1,%2,%3}, [%4];"
                 : "=r"(r[0]), "=r"(r[1]), "=r"(r[2]), "=r"(r[3]) : "r"(addr));
}
__device__ __forceinline__ void ldsm_x4_t(uint32_t (&r)[4], uint32_t addr) {
    asm volatile("ldmatrix.sync.aligned.m8n8.x4.trans.shared.b16 {%0,%1,%2,%3}, [%4];"
                 : "=r"(r[0]), "=r"(r[1]), "=r"(r[2]), "=r"(r[3]) : "r"(addr));
}

__device__ __forceinline__ void mma16816(float (&d)[4], const uint32_t (&a)[4],
                                         uint32_t b0, uint32_t b1) {
    asm volatile(
        "mma.sync.aligned.m16n8k16.row.col.f32.f16.f16.f32 "
        "{%0,%1,%2,%3}, {%4,%5,%6,%7}, {%8,%9}, {%0,%1,%2,%3};"
        : "+f"(d[0]), "+f"(d[1]), "+f"(d[2]), "+f"(d[3])
        : "r"(a[0]), "r"(a[1]), "r"(a[2]), "r"(a[3]), "r"(b0), "r"(b1));
}

__device__ __forceinline__ void split2h(float x, __half& h, __half& l) {
    h = __float2half_rn(x);
    l = __float2half_rn(x - __half2float(h));
}

// ============================================================
// Fused depthwise 3x3 convs. Blocks [0, B*C) do q; [B*C, B*C+B*K) do k+v.
// q,k get hi/lo fp16 split (feed gemm1 3-pass); v is plain fp16 (gemm2 1-pass).
// ============================================================
__global__ __launch_bounds__(256) void dwconv_all_kernel(
    const float* __restrict__ xq, const float* __restrict__ xkv,
    const float* __restrict__ wq, const float* __restrict__ bq,
    const float* __restrict__ wk, const float* __restrict__ bk,
    const float* __restrict__ wv, const float* __restrict__ bv) {
    __shared__ float tile[66 * 66];
    const int blk = blockIdx.x;
    const bool isq = blk < B_ * C_;
    const int bc = isq ? blk : blk - B_ * C_;
    const int c  = isq ? (bc & (C_ - 1)) : (bc & (KA - 1));
    const float* xp = (isq ? xq : xkv) + (size_t)bc * N_;
    for (int i = threadIdx.x; i < 66 * 66; i += 256) {
        int r = i / 66 - 1, cc = i % 66 - 1;
        tile[i] = (r >= 0 && r < 64 && cc >= 0 && cc < 64) ? xp[r * 64 + cc] : 0.f;
    }
    if (isq) {
        const float w0 = wq[c*9+0], w1 = wq[c*9+1], w2 = wq[c*9+2];
        const float w3 = wq[c*9+3], w4 = wq[c*9+4], w5 = wq[c*9+5];
        const float w6 = wq[c*9+6], w7 = wq[c*9+7], w8 = wq[c*9+8];
        const float bb = bq[c];
        __syncthreads();
        __half* yh = g_qh + (size_t)bc * N_;
        __half* yl = g_ql + (size_t)bc * N_;
        for (int p = threadIdx.x; p < N_; p += 256) {
            int r = p >> 6, cc = p & 63;
            const float* t = tile + r * 66 + cc;
            float s = bb;
            s = fmaf(w0, t[0],   s); s = fmaf(w1, t[1],   s); s = fmaf(w2, t[2],   s);
            s = fmaf(w3, t[66],  s); s = fmaf(w4, t[67],  s); s = fmaf(w5, t[68],  s);
            s = fmaf(w6, t[132], s); s = fmaf(w7, t[133], s); s = fmaf(w8, t[134], s);
            __half h, l; split2h(s, h, l);
            yh[p] = h; yl[p] = l;
        }
    } else {
        const float k0 = wk[c*9+0], k1 = wk[c*9+1], k2 = wk[c*9+2];
        const float k3 = wk[c*9+3], k4 = wk[c*9+4], k5 = wk[c*9+5];
        const float k6 = wk[c*9+6], k7 = wk[c*9+7], k8 = wk[c*9+8];
        const float v0 = wv[c*9+0], v1 = wv[c*9+1], v2 = wv[c*9+2];
        const float v3 = wv[c*9+3], v4 = wv[c*9+4], v5 = wv[c*9+5];
        const float v6 = wv[c*9+6], v7 = wv[c*9+7], v8 = wv[c*9+8];
        const float bbk = bk[c], bbv = bv[c];
        __syncthreads();
        __half* kh = g_kh + (size_t)bc * N_;
        __half* kl = g_kl + (size_t)bc * N_;
        __half* vh = g_vh + (size_t)bc * N_;
        for (int p = threadIdx.x; p < N_; p += 256) {
            int r = p >> 6, cc = p & 63;
            const float* t = tile + r * 66 + cc;
            float sk = bbk, sv = bbv;
            sk = fmaf(k0, t[0],   sk); sk = fmaf(k1, t[1],   sk); sk = fmaf(k2, t[2],   sk);
            sk = fmaf(k3, t[66],  sk); sk = fmaf(k4, t[67],  sk); sk = fmaf(k5, t[68],  sk);
            sk = fmaf(k6, t[132], sk); sk = fmaf(k7, t[133], sk); sk = fmaf(k8, t[134], sk);
            sv = fmaf(v0, t[0],   sv); sv = fmaf(v1, t[1],   sv); sv = fmaf(v2, t[2],   sv);
            sv = fmaf(v3, t[66],  sv); sv = fmaf(v4, t[67],  sv); sv = fmaf(v5, t[68],  sv);
            sv = fmaf(v6, t[132], sv); sv = fmaf(v7, t[133], sv); sv = fmaf(v8, t[134], sv);
            __half h, l;
            split2h(sk, h, l); kh[p] = h; kl[p] = l;
            vh[p] = __float2half_rn(sv);
        }
    }
}

// ============================================================
// GEMM1 (split-K=4): part[ks][b][c][k] = sum_{n in ks-slice} q[c,n]*kmat[k,n]
// mma.sync fp16 3-pass. CTA tile 64x64, k-chunk 64, double-buffered cp.async.
// grid (B, mt=8, z=8: nt=z&1, ks=z>>1). 4 warps, warp tile 32x32, occ 3.
// (FROZEN — measured best rounds 5/7/9/12/14)
// ============================================================
#define G1_PAD  72
#define G1_ASZ  (64 * G1_PAD)
#define G1_BUFE (4 * G1_ASZ)
#define G1_SMEM (2 * G1_BUFE * 2)
#define G1_NIT  16

__global__ __launch_bounds__(128, 3) void gemm1_mma() {
    extern __shared__ __half sm1[];
    const int t = threadIdx.x, lane = t & 31, wid = t >> 5;
    const int wm = wid >> 1, wn = wid & 1;
    const int b = blockIdx.x, mt = blockIdx.y;
    const int nt = blockIdx.z & 1, ks = blockIdx.z >> 1;
    const int kbase = ks * 1024;
    const uint32_t sb = smem_u32(sm1);

    const __half* gsrc[4] = {
        g_qh + ((size_t)(b * C_ + mt * 64)) * N_,
        g_ql + ((size_t)(b * C_ + mt * 64)) * N_,
        g_kh + ((size_t)b * KA + nt * 64) * N_,
        g_kl + ((size_t)b * KA + nt * 64) * N_ };

    auto fill = [&](int bi, int n0) {
        uint32_t dbase = sb + bi * (G1_BUFE * 2);
        #pragma unroll
        for (int a = 0; a < 4; a++) {
            const __half* src = gsrc[a];
            uint32_t abase = dbase + a * (G1_ASZ * 2);
            #pragma unroll
            for (int i = 0; i < 4; i++) {
                int idx = t + 128 * i;                 // 0..511
                int row = idx >> 3, ch = (idx & 7) << 3;
                CP_ASYNC16(abase + (uint32_t)(row * G1_PAD + ch) * 2,
                           src + (size_t)row * N_ + n0 + ch);
            }
        }
    };

    fill(0, kbase);       CP_COMMIT();
    fill(1, kbase + 64);  CP_COMMIT();

    float acc[2][4][4];
    #pragma unroll
    for (int i = 0; i < 2; i++)
        #pragma unroll
        for (int j = 0; j < 4; j++)
            #pragma unroll
            for (int e = 0; e < 4; e++) acc[i][j][e] = 0.f;

    const int ar = lane & 15,                       ac = (lane >> 4) << 3;
    const int br = (lane & 7) | ((lane >> 4) << 3), bc = ((lane >> 3) & 1) << 3;

    for (int it = 0; it < G1_NIT; it++) {
        CP_WAIT1();
        __syncthreads();
        const uint32_t bufb = sb + (it & 1) * (G1_BUFE * 2);
        const uint32_t Ah = bufb, Al = bufb + G1_ASZ * 2;
        const uint32_t Bh = bufb + 2 * G1_ASZ * 2, Bl = bufb + 3 * G1_ASZ * 2;
        #pragma unroll
        for (int kk = 0; kk < 4; kk++) {
            const int k0 = kk * 16;
            uint32_t ah[2][4], al[2][4], bh[2][4], bl[2][4];
            #pragma unroll
            for (int fm = 0; fm < 2; fm++) {
                uint32_t off = (uint32_t)((wm * 32 + fm * 16 + ar) * G1_PAD + k0 + ac) * 2;
                ldsm_x4(ah[fm], Ah + off);
                ldsm_x4(al[fm], Al + off);
            }
            #pragma unroll
            for (int g = 0; g < 2; g++) {
                uint32_t off = (uint32_t)((wn * 32 + g * 16 + br) * G1_PAD + k0 + bc) * 2;
                ldsm_x4(bh[g], Bh + off);
                ldsm_x4(bl[g], Bl + off);
            }
            #pragma unroll
            for (int fm = 0; fm < 2; fm++)
                #pragma unroll
                for (int fn = 0; fn < 4; fn++) {
                    const int g = fn >> 1, p = (fn & 1) * 2;
                    mma16816(acc[fm][fn], ah[fm], bh[g][p], bh[g][p + 1]);
                    mma16816(acc[fm][fn], ah[fm], bl[g][p], bl[g][p + 1]);
                    mma16816(acc[fm][fn], al[fm], bh[g][p], bh[g][p + 1]);
                }
        }
        __syncthreads();
        if (it + 2 < G1_NIT) fill(it & 1, kbase + (it + 2) * 64);
        CP_COMMIT();
    }
    CP_WAIT0();

    float* base = g_part + ((size_t)(ks * B_ + b) * C_) * KA;
    #pragma unroll
    for (int fm = 0; fm < 2; fm++) {
        int r0 = mt * 64 + wm * 32 + fm * 16 + (lane >> 2);
        #pragma unroll
        for (int fn = 0; fn < 4; fn++) {
            int cc = nt * 64 + wn * 32 + fn * 8 + (lane & 3) * 2;
            float* d0 = base + (size_t)r0 * KA + cc;
            d0[0] = acc[fm][fn][0];
            d0[1] = acc[fm][fn][1];
            float* d1 = d0 + 8 * KA;
            d1[0] = acc[fm][fn][2];
            d1[1] = acc[fm][fn][3];
        }
    }
}

// ============================================================
// Split-K reduce + scale + softmax. 4 rows per 512-thread block.
// ============================================================
__global__ __launch_bounds__(512) void reduce_softmax_kernel(float* __restrict__ AW) {
    const int t   = threadIdx.x;
    const int g   = t >> 7;              // row group 0..3
    const int tid = t & 127;             // lane within row
    const int bc  = blockIdx.x * 4 + g;
    float v = 0.f;
    #pragma unroll
    for (int ps = 0; ps < 4; ps++)
        v += g_part[((size_t)ps * B_ * C_ + bc) * KA + tid];
    v *= 0.0883883476483184f;            // 1/sqrt(128)
    __shared__ float red[4][4];
    float m = v;
    #pragma unroll
    for (int o = 16; o; o >>= 1) m = fmaxf(m, __shfl_xor_sync(0xffffffffu, m, o));
    if ((tid & 31) == 0) red[g][(tid >> 5)] = m;
    __syncthreads();
    m = fmaxf(fmaxf(red[g][0], red[g][1]), fmaxf(red[g][2], red[g][3]));
    float e = expf(v - m);
    float s = e;
    #pragma unroll
    for (int o = 16; o; o >>= 1) s += __shfl_xor_sync(0xffffffffu, s, o);
    __syncthreads();
    if ((tid & 31) == 0) red[g][(tid >> 5)] = s;
    __syncthreads();
    s = red[g][0] + red[g][1] + red[g][2] + red[g][3];
    AW[(size_t)bc * KA + tid] = e / s;
}

// ============================================================
// Top-51-of-512 mask v3: coalesced smem staging + warp-per-column select.
// (FROZEN — round-13 measured: 10.4 us)
// ============================================================
__global__ __launch_bounds__(256) void topk_mask_kernel(float* __restrict__ AW) {
    __shared__ float s[512 * 9];
    const int b  = blockIdx.x >> 4;
    const int kg = (blockIdx.x & 15) * 8;
    const int t  = threadIdx.x;
    const int wid = t >> 5, lane = t & 31;

    #pragma unroll
    for (int i = 0; i < 16; i++) {
        int idx = t + 256 * i;             // 0..4095
        int c = idx >> 3, j = idx & 7;
        s[c * 9 + j] = AW[((size_t)(b * C_ + c)) * KA + kg + j];
    }
    __syncthreads();

    {
        const int j = wid;                 // 1 column per warp
        unsigned u[16];
        #pragma unroll
        for (int i = 0; i < 16; i++) {
            unsigned x = __float_as_uint(s[(lane + 32 * i) * 9 + j]);
            u[i] = (x & 0x80000000u) ? ~x : (x | 0x80000000u);
        }
        unsigned thr = 0x80000000u;
        for (int bit = 29; bit >= 0; bit--) {
            unsigned cand = thr | (1u << bit);
            int cnt = 0;
            #pragma unroll
            for (int i = 0; i < 16; i++) cnt += (u[i] >= cand);
            #pragma unroll
            for (int o = 16; o; o >>= 1) cnt += __shfl_xor_sync(0xffffffffu, cnt, o);
            if (cnt >= NKEEP) {
                thr = cand;
                if (cnt == NKEEP) break;   // warp-uniform early exit
            }
        }
        #pragma unroll
        for (int i = 0; i < 16; i++)
            if (u[i] < thr) s[(lane + 32 * i) * 9 + j] = 0.f;
    }
    __syncthreads();

    #pragma unroll
    for (int i = 0; i < 16; i++) {
        int idx = t + 256 * i;
        int c = idx >> 3, j = idx & 7;
        AW[((size_t)(b * C_ + c)) * KA + kg + j] = s[c * 9 + j];
    }
}

// ============================================================
// GEMM2 (1-pass, pure fp16): out[b,c,n] = x_q[b,c,n] + sum_k aw[c,k]*v[k,n]
// aw fp16, v fp16 (no lo). CTA 64(m) x 128(n), K=128 single shot,
// B via cp.async + ldmatrix.trans. 8 warps (2m x 4n), warp tile 32x32.
// grid (B, 8, 32). smem 51KB -> 3 CTA/SM.
// ============================================================
#define G2_PAD   136
#define G2_A_E   (64 * G2_PAD)
#define G2_B_E   (128 * G2_PAD)
#define G2_SMEM  ((G2_A_E + G2_B_E) * 2)

__global__ __launch_bounds__(256, 3) void gemm2_mma(
    const float* __restrict__ AW, const float* __restrict__ XQ,
    float* __restrict__ OUT) {
    extern __shared__ __half sm2[];
    __half* Ah = sm2;
    const int t = threadIdx.x, lane = t & 31, wid = t >> 5;
    const int wm = wid >> 2, wn = wid & 3;
    const int b = blockIdx.x, mt = blockIdx.y, nt = blockIdx.z;
    const uint32_t sb = smem_u32(sm2);

    // B: cp.async v tile [k=128][n=128] (natural layout)
    {
        const __half* sh = g_vh + (size_t)b * KA * N_ + nt * 128;
        const uint32_t bh0 = sb + G2_A_E * 2;
        #pragma unroll
        for (int i = 0; i < 8; i++) {
            int idx = t + 256 * i;                 // 0..2047
            int row = idx >> 4, ch = (idx & 15) << 3;
            CP_ASYNC16(bh0 + (uint32_t)(row * G2_PAD + ch) * 2,
                       sh + (size_t)row * N_ + ch);
        }
        CP_COMMIT();
    }
    // A: convert aw (fp32, post-mask) to fp16 (overlaps B cp.async)
    {
        const float* asrc = AW + ((size_t)(b * C_ + mt * 64)) * KA;
        #pragma unroll
        for (int i = 0; i < 8; i++) {
            int idx = t + 256 * i;                 // 0..2047
            int row = idx >> 5, c4 = (idx & 31) << 2;
            float4 v = *reinterpret_cast<const float4*>(asrc + (size_t)row * KA + c4);
            __half* dh = Ah + row * G2_PAD + c4;
            dh[0] = __float2half_rn(v.x);
            dh[1] = __float2half_rn(v.y);
            dh[2] = __float2half_rn(v.z);
            dh[3] = __float2half_rn(v.w);
        }
    }
    CP_WAIT0();
    __syncthreads();

    float acc[2][4][4];
    #pragma unroll
    for (int i = 0; i < 2; i++)
        #pragma unroll
        for (int j = 0; j < 4; j++)
            #pragma unroll
            for (int e = 0; e < 4; e++) acc[i][j][e] = 0.f;

    const uint32_t oAh = 0;
    const uint32_t oBh = G2_A_E * 2;
    const int ar = lane & 15, axc = (lane >> 4) << 3;

    #pragma unroll
    for (int kk = 0; kk < 8; kk++) {
        const int k0 = kk * 16;
        uint32_t ah[2][4], bh[2][4];
        #pragma unroll
        for (int fm = 0; fm < 2; fm++) {
            uint32_t off = (uint32_t)((wm * 32 + fm * 16 + ar) * G2_PAD + k0 + axc) * 2;
            ldsm_x4(ah[fm], sb + oAh + off);
        }
        #pragma unroll
        for (int g = 0; g < 2; g++) {
            uint32_t off = (uint32_t)((k0 + ar) * G2_PAD + wn * 32 + g * 16 + axc) * 2;
            ldsm_x4_t(bh[g], sb + oBh + off);
        }
        #pragma unroll
        for (int fm = 0; fm < 2; fm++)
            #pragma unroll
            for (int fn = 0; fn < 4; fn++) {
                const int g = fn >> 1, p = (fn & 1) * 2;
                mma16816(acc[fm][fn], ah[fm], bh[g][p], bh[g][p + 1]);
            }
    }

    #pragma unroll
    for (int fm = 0; fm < 2; fm++) {
        int r0 = mt * 64 + wm * 32 + fm * 16 + (lane >> 2);
        #pragma unroll
        for (int fn = 0; fn < 4; fn++) {
            int cc = nt * 128 + wn * 32 + fn * 8 + (lane & 3) * 2;
            size_t off0 = ((size_t)(b * C_ + r0)) * N_ + cc;
            float2 x0 = *reinterpret_cast<const float2*>(XQ + off0);
            float2 o0 = make_float2(x0.x + acc[fm][fn][0], x0.y + acc[fm][fn][1]);
            *reinterpret_cast<float2*>(OUT + off0) = o0;
            size_t off1 = off0 + (size_t)8 * N_;
            float2 x1 = *reinterpret_cast<const float2*>(XQ + off1);
            float2 o1 = make_float2(x1.x + acc[fm][fn][2], x1.y + acc[fm][fn][3]);
            *reinterpret_cast<float2*>(OUT + off1) = o1;
        }
    }
}

// ============================================================
extern "C" void kernel_launch(void* const* d_in, const int* in_sizes, int n_in,
                              void* d_out, int out_size) {
    const float* x_q  = (const float*)d_in[0];
    const float* x_kv = (const float*)d_in[1];
    const float* wq   = (const float*)d_in[2];
    const float* bq   = (const float*)d_in[3];
    const float* wk   = (const float*)d_in[4];
    const float* bk   = (const float*)d_in[5];
    const float* wv   = (const float*)d_in[6];
    const float* bv   = (const float*)d_in[7];

    float* out1 = (float*)d_out;                   // [B,C,H,W]
    float* aw   = out1 + (size_t)B_ * C_ * N_;     // [B,C,K]

    static int configured = 0;
    if (!configured) {
        cudaFuncSetAttribute(gemm1_mma,
                             cudaFuncAttributeMaxDynamicSharedMemorySize, G1_SMEM);
        cudaFuncSetAttribute(gemm2_mma,
                             cudaFuncAttributeMaxDynamicSharedMemorySize, G2_SMEM);
        configured = 1;
    }

    dwconv_all_kernel    <<<B_ * C_ + B_ * KA, 256>>>(x_q, x_kv, wq, bq, wk, bk, wv, bv);
    gemm1_mma            <<<dim3(B_, 8, 8), 128, G1_SMEM>>>();
    reduce_softmax_kernel<<<B_ * C_ / 4, 512>>>(aw);
    topk_mask_kernel     <<<B_ * 16, 256>>>(aw);
    gemm2_mma            <<<dim3(B_, 8, 32), 256, G2_SMEM>>>(aw, x_q, out1);
}

// round 16
// speedup vs baseline: 1.1020x; 1.0241x over previous
#include <cuda_runtime.h>
#include <cuda_fp16.h>
#include <cstdint>

#define B_    16
#define C_    512
#define KA    128
#define N_    4096
#define NKEEP 51

// ---------------- scratch (device globals; no allocation allowed) --------
__device__ __half g_qh [(size_t)B_ * C_ * N_];   // 64 MiB
__device__ __half g_ql [(size_t)B_ * C_ * N_];   // 64 MiB
__device__ __half g_kh [(size_t)B_ * KA * N_];   // 16 MiB
__device__ __half g_kl [(size_t)B_ * KA * N_];   // 16 MiB
__device__ __half g_vh [(size_t)B_ * KA * N_];   // 16 MiB  [b][k][n]
__device__ float  g_part[(size_t)4 * B_ * C_ * KA];  // 16 MiB split-K partials

// ---------------- helpers -------------------------------------------------
__device__ __forceinline__ uint32_t smem_u32(const void* p) {
    uint32_t a;
    asm("{ .reg .u64 t; cvta.to.shared.u64 t, %1; cvt.u32.u64 %0, t; }"
        : "=r"(a) : "l"(p));
    return a;
}

#define CP_ASYNC16(saddr, gptr) \
    asm volatile("cp.async.cg.shared.global [%0], [%1], 16;" :: "r"(saddr), "l"(gptr))
#define CP_COMMIT() asm volatile("cp.async.commit_group;" ::: "memory")
#define CP_WAIT1()  asm volatile("cp.async.wait_group 1;" ::: "memory")
#define CP_WAIT0()  asm volatile("cp.async.wait_group 0;" ::: "memory")

__device__ __forceinline__ void ldsm_x4(uint32_t (&r)[4], uint32_t addr) {
    asm volatile("ldmatrix.sync.aligned.m8n8.x4.shared.b16 {%0,%1,%2,%3}, [%4];"
                 : "=r"(r[0]), "=r"(r[1]), "=r"(r[2]), "=r"(r[3]) : "r"(addr));
}
__device__ __forceinline__ void ldsm_x4_t(uint32_t (&r)[4], uint32_t addr) {
    asm volatile("ldmatrix.sync.aligned.m8n8.x4.trans.shared.b16 {%0,%1,%2,%3}, [%4];"
                 : "=r"(r[0]), "=r"(r[1]), "=r"(r[2]), "=r"(r[3]) : "r"(addr));
}

__device__ __forceinline__ void mma16816(float (&d)[4], const uint32_t (&a)[4],
                                         uint32_t b0, uint32_t b1) {
    asm volatile(
        "mma.sync.aligned.m16n8k16.row.col.f32.f16.f16.f32 "
        "{%0,%1,%2,%3}, {%4,%5,%6,%7}, {%8,%9}, {%0,%1,%2,%3};"
        : "+f"(d[0]), "+f"(d[1]), "+f"(d[2]), "+f"(d[3])
        : "r"(a[0]), "r"(a[1]), "r"(a[2]), "r"(a[3]), "r"(b0), "r"(b1));
}

__device__ __forceinline__ void split2h(float x, __half& h, __half& l) {
    h = __float2half_rn(x);
    l = __float2half_rn(x - __half2float(h));
}

// ============================================================
// Fused depthwise 3x3 convs. Blocks [0, B*C) do q; [B*C, B*C+B*K) do k+v.
// q,k get hi/lo fp16 split (gemm1 3-pass); v plain fp16 (gemm2 1-pass).
// (FROZEN — round-15 measured)
// ============================================================
__global__ __launch_bounds__(256) void dwconv_all_kernel(
    const float* __restrict__ xq, const float* __restrict__ xkv,
    const float* __restrict__ wq, const float* __restrict__ bq,
    const float* __restrict__ wk, const float* __restrict__ bk,
    const float* __restrict__ wv, const float* __restrict__ bv) {
    __shared__ float tile[66 * 66];
    const int blk = blockIdx.x;
    const bool isq = blk < B_ * C_;
    const int bc = isq ? blk : blk - B_ * C_;
    const int c  = isq ? (bc & (C_ - 1)) : (bc & (KA - 1));
    const float* xp = (isq ? xq : xkv) + (size_t)bc * N_;
    for (int i = threadIdx.x; i < 66 * 66; i += 256) {
        int r = i / 66 - 1, cc = i % 66 - 1;
        tile[i] = (r >= 0 && r < 64 && cc >= 0 && cc < 64) ? xp[r * 64 + cc] : 0.f;
    }
    if (isq) {
        const float w0 = wq[c*9+0], w1 = wq[c*9+1], w2 = wq[c*9+2];
        const float w3 = wq[c*9+3], w4 = wq[c*9+4], w5 = wq[c*9+5];
        const float w6 = wq[c*9+6], w7 = wq[c*9+7], w8 = wq[c*9+8];
        const float bb = bq[c];
        __syncthreads();
        __half* yh = g_qh + (size_t)bc * N_;
        __half* yl = g_ql + (size_t)bc * N_;
        for (int p = threadIdx.x; p < N_; p += 256) {
            int r = p >> 6, cc = p & 63;
            const float* t = tile + r * 66 + cc;
            float s = bb;
            s = fmaf(w0, t[0],   s); s = fmaf(w1, t[1],   s); s = fmaf(w2, t[2],   s);
            s = fmaf(w3, t[66],  s); s = fmaf(w4, t[67],  s); s = fmaf(w5, t[68],  s);
            s = fmaf(w6, t[132], s); s = fmaf(w7, t[133], s); s = fmaf(w8, t[134], s);
            __half h, l; split2h(s, h, l);
            yh[p] = h; yl[p] = l;
        }
    } else {
        const float k0 = wk[c*9+0], k1 = wk[c*9+1], k2 = wk[c*9+2];
        const float k3 = wk[c*9+3], k4 = wk[c*9+4], k5 = wk[c*9+5];
        const float k6 = wk[c*9+6], k7 = wk[c*9+7], k8 = wk[c*9+8];
        const float v0 = wv[c*9+0], v1 = wv[c*9+1], v2 = wv[c*9+2];
        const float v3 = wv[c*9+3], v4 = wv[c*9+4], v5 = wv[c*9+5];
        const float v6 = wv[c*9+6], v7 = wv[c*9+7], v8 = wv[c*9+8];
        const float bbk = bk[c], bbv = bv[c];
        __syncthreads();
        __half* kh = g_kh + (size_t)bc * N_;
        __half* kl = g_kl + (size_t)bc * N_;
        __half* vh = g_vh + (size_t)bc * N_;
        for (int p = threadIdx.x; p < N_; p += 256) {
            int r = p >> 6, cc = p & 63;
            const float* t = tile + r * 66 + cc;
            float sk = bbk, sv = bbv;
            sk = fmaf(k0, t[0],   sk); sk = fmaf(k1, t[1],   sk); sk = fmaf(k2, t[2],   sk);
            sk = fmaf(k3, t[66],  sk); sk = fmaf(k4, t[67],  sk); sk = fmaf(k5, t[68],  sk);
            sk = fmaf(k6, t[132], sk); sk = fmaf(k7, t[133], sk); sk = fmaf(k8, t[134], sk);
            sv = fmaf(v0, t[0],   sv); sv = fmaf(v1, t[1],   sv); sv = fmaf(v2, t[2],   sv);
            sv = fmaf(v3, t[66],  sv); sv = fmaf(v4, t[67],  sv); sv = fmaf(v5, t[68],  sv);
            sv = fmaf(v6, t[132], sv); sv = fmaf(v7, t[133], sv); sv = fmaf(v8, t[134], sv);
            __half h, l;
            split2h(sk, h, l); kh[p] = h; kl[p] = l;
            vh[p] = __float2half_rn(sv);
        }
    }
}

// ============================================================
// GEMM1 (split-K=4): part[ks][b][c][k] = sum_{n in ks-slice} q[c,n]*kmat[k,n]
// mma.sync fp16 3-pass. CTA tile 64x64, k-chunk 64, double-buffered cp.async.
// grid (B, mt=8, z=8: nt=z&1, ks=z>>1). 4 warps, warp tile 32x32, occ 3.
// (FROZEN — measured best rounds 5/7/9/12/14/15)
// ============================================================
#define G1_PAD  72
#define G1_ASZ  (64 * G1_PAD)
#define G1_BUFE (4 * G1_ASZ)
#define G1_SMEM (2 * G1_BUFE * 2)
#define G1_NIT  16

__global__ __launch_bounds__(128, 3) void gemm1_mma() {
    extern __shared__ __half sm1[];
    const int t = threadIdx.x, lane = t & 31, wid = t >> 5;
    const int wm = wid >> 1, wn = wid & 1;
    const int b = blockIdx.x, mt = blockIdx.y;
    const int nt = blockIdx.z & 1, ks = blockIdx.z >> 1;
    const int kbase = ks * 1024;
    const uint32_t sb = smem_u32(sm1);

    const __half* gsrc[4] = {
        g_qh + ((size_t)(b * C_ + mt * 64)) * N_,
        g_ql + ((size_t)(b * C_ + mt * 64)) * N_,
        g_kh + ((size_t)b * KA + nt * 64) * N_,
        g_kl + ((size_t)b * KA + nt * 64) * N_ };

    auto fill = [&](int bi, int n0) {
        uint32_t dbase = sb + bi * (G1_BUFE * 2);
        #pragma unroll
        for (int a = 0; a < 4; a++) {
            const __half* src = gsrc[a];
            uint32_t abase = dbase + a * (G1_ASZ * 2);
            #pragma unroll
            for (int i = 0; i < 4; i++) {
                int idx = t + 128 * i;                 // 0..511
                int row = idx >> 3, ch = (idx & 7) << 3;
                CP_ASYNC16(abase + (uint32_t)(row * G1_PAD + ch) * 2,
                           src + (size_t)row * N_ + n0 + ch);
            }
        }
    };

    fill(0, kbase);       CP_COMMIT();
    fill(1, kbase + 64);  CP_COMMIT();

    float acc[2][4][4];
    #pragma unroll
    for (int i = 0; i < 2; i++)
        #pragma unroll
        for (int j = 0; j < 4; j++)
            #pragma unroll
            for (int e = 0; e < 4; e++) acc[i][j][e] = 0.f;

    const int ar = lane & 15,                       ac = (lane >> 4) << 3;
    const int br = (lane & 7) | ((lane >> 4) << 3), bc = ((lane >> 3) & 1) << 3;

    for (int it = 0; it < G1_NIT; it++) {
        CP_WAIT1();
        __syncthreads();
        const uint32_t bufb = sb + (it & 1) * (G1_BUFE * 2);
        const uint32_t Ah = bufb, Al = bufb + G1_ASZ * 2;
        const uint32_t Bh = bufb + 2 * G1_ASZ * 2, Bl = bufb + 3 * G1_ASZ * 2;
        #pragma unroll
        for (int kk = 0; kk < 4; kk++) {
            const int k0 = kk * 16;
            uint32_t ah[2][4], al[2][4], bh[2][4], bl[2][4];
            #pragma unroll
            for (int fm = 0; fm < 2; fm++) {
                uint32_t off = (uint32_t)((wm * 32 + fm * 16 + ar) * G1_PAD + k0 + ac) * 2;
                ldsm_x4(ah[fm], Ah + off);
                ldsm_x4(al[fm], Al + off);
            }
            #pragma unroll
            for (int g = 0; g < 2; g++) {
                uint32_t off = (uint32_t)((wn * 32 + g * 16 + br) * G1_PAD + k0 + bc) * 2;
                ldsm_x4(bh[g], Bh + off);
                ldsm_x4(bl[g], Bl + off);
            }
            #pragma unroll
            for (int fm = 0; fm < 2; fm++)
                #pragma unroll
                for (int fn = 0; fn < 4; fn++) {
                    const int g = fn >> 1, p = (fn & 1) * 2;
                    mma16816(acc[fm][fn], ah[fm], bh[g][p], bh[g][p + 1]);
                    mma16816(acc[fm][fn], ah[fm], bl[g][p], bl[g][p + 1]);
                    mma16816(acc[fm][fn], al[fm], bh[g][p], bh[g][p + 1]);
                }
        }
        __syncthreads();
        if (it + 2 < G1_NIT) fill(it & 1, kbase + (it + 2) * 64);
        CP_COMMIT();
    }
    CP_WAIT0();

    float* base = g_part + ((size_t)(ks * B_ + b) * C_) * KA;
    #pragma unroll
    for (int fm = 0; fm < 2; fm++) {
        int r0 = mt * 64 + wm * 32 + fm * 16 + (lane >> 2);
        #pragma unroll
        for (int fn = 0; fn < 4; fn++) {
            int cc = nt * 64 + wn * 32 + fn * 8 + (lane & 3) * 2;
            float* d0 = base + (size_t)r0 * KA + cc;
            d0[0] = acc[fm][fn][0];
            d0[1] = acc[fm][fn][1];
            float* d1 = d0 + 8 * KA;
            d1[0] = acc[fm][fn][2];
            d1[1] = acc[fm][fn][3];
        }
    }
}

// ============================================================
// Split-K reduce + scale + softmax: warp-autonomous, barrier-free.
// 1024 blocks x 256 threads; warp w handles row bc = blockIdx*8+w.
// Lane owns 4 k's (float4 per slab). shfl-only reductions.
// ============================================================
__global__ __launch_bounds__(256) void reduce_softmax_kernel(float* __restrict__ AW) {
    const int wid  = threadIdx.x >> 5, lane = threadIdx.x & 31;
    const int bc   = blockIdx.x * 8 + wid;
    float4 v = make_float4(0.f, 0.f, 0.f, 0.f);
    #pragma unroll
    for (int ps = 0; ps < 4; ps++) {
        const float4 p = *reinterpret_cast<const float4*>(
            g_part + ((size_t)ps * B_ * C_ + bc) * KA + lane * 4);
        v.x += p.x; v.y += p.y; v.z += p.z; v.w += p.w;
    }
    const float sc = 0.0883883476483184f;   // 1/sqrt(128)
    v.x *= sc; v.y *= sc; v.z *= sc; v.w *= sc;
    float m = fmaxf(fmaxf(v.x, v.y), fmaxf(v.z, v.w));
    #pragma unroll
    for (int o = 16; o; o >>= 1) m = fmaxf(m, __shfl_xor_sync(0xffffffffu, m, o));
    float4 e;
    e.x = expf(v.x - m); e.y = expf(v.y - m);
    e.z = expf(v.z - m); e.w = expf(v.w - m);
    float s = e.x + e.y + e.z + e.w;
    #pragma unroll
    for (int o = 16; o; o >>= 1) s += __shfl_xor_sync(0xffffffffu, s, o);
    const float inv = 1.f / s;
    e.x *= inv; e.y *= inv; e.z *= inv; e.w *= inv;
    *reinterpret_cast<float4*>(AW + (size_t)bc * KA + lane * 4) = e;
}

// ============================================================
// Top-51-of-512 mask v4: coalesced smem staging + warp-per-column
// RADIX-4 select (3 independent count chains per 2-bit step -> ~half
// the serialized shfl depth). Selection result identical to radix-2.
// 256 blocks x 256 threads; block (b, kg) owns slab aw[b][0:512][kg*8:+8].
// ============================================================
__global__ __launch_bounds__(256) void topk_mask_kernel(float* __restrict__ AW) {
    __shared__ float s[512 * 9];
    const int b  = blockIdx.x >> 4;
    const int kg = (blockIdx.x & 15) * 8;
    const int t  = threadIdx.x;
    const int wid = t >> 5, lane = t & 31;

    // staged load: float4 per thread (rows of 8 = 2 float4)
    #pragma unroll
    for (int i = 0; i < 4; i++) {
        int idx = t + 256 * i;             // 0..1023 float4s
        int c = idx >> 1, j4 = (idx & 1) << 2;
        float4 v = *reinterpret_cast<const float4*>(
            AW + ((size_t)(b * C_ + c)) * KA + kg + j4);
        float* d = s + c * 9 + j4;
        d[0] = v.x; d[1] = v.y; d[2] = v.z; d[3] = v.w;
    }
    __syncthreads();

    {
        const int j = wid;                 // 1 column per warp
        unsigned u[16];
        #pragma unroll
        for (int i = 0; i < 16; i++) {
            unsigned x = __float_as_uint(s[(lane + 32 * i) * 9 + j]);
            u[i] = (x & 0x80000000u) ? ~x : (x | 0x80000000u);
        }
        unsigned thr = 0x80000000u;
        #pragma unroll 1
        for (int bit = 28; bit >= 0; bit -= 2) {     // 15 two-bit steps (bits 29..0)
            unsigned c1 = thr | (1u << bit);
            unsigned c2 = thr | (2u << bit);
            unsigned c3 = thr | (3u << bit);
            int n1 = 0, n2 = 0, n3 = 0;
            #pragma unroll
            for (int i = 0; i < 16; i++) {
                n1 += (u[i] >= c1);
                n2 += (u[i] >= c2);
                n3 += (u[i] >= c3);
            }
            #pragma unroll
            for (int o = 16; o; o >>= 1) {
                n1 += __shfl_xor_sync(0xffffffffu, n1, o);
                n2 += __shfl_xor_sync(0xffffffffu, n2, o);
                n3 += __shfl_xor_sync(0xffffffffu, n3, o);
            }
            if (n3 >= NKEEP)      { thr = c3; if (n3 == NKEEP) break; }
            else if (n2 >= NKEEP) { thr = c2; if (n2 == NKEEP) break; }
            else if (n1 >= NKEEP) { thr = c1; if (n1 == NKEEP) break; }
        }
        #pragma unroll
        for (int i = 0; i < 16; i++)
            if (u[i] < thr) s[(lane + 32 * i) * 9 + j] = 0.f;
    }
    __syncthreads();

    // staged write-back
    #pragma unroll
    for (int i = 0; i < 4; i++) {
        int idx = t + 256 * i;
        int c = idx >> 1, j4 = (idx & 1) << 2;
        const float* d = s + c * 9 + j4;
        float4 v = make_float4(d[0], d[1], d[2], d[3]);
        *reinterpret_cast<float4*>(AW + ((size_t)(b * C_ + c)) * KA + kg + j4) = v;
    }
}

// ============================================================
// GEMM2 (1-pass, pure fp16): out[b,c,n] = x_q[b,c,n] + sum_k aw[c,k]*v[k,n]
// CTA 64(m) x 128(n), K=128 single shot, B via cp.async + ldmatrix.trans.
// 8 warps (2m x 4n), warp tile 32x32. grid (B, 8, 32). smem 51KB -> 3 CTA/SM.
// (FROZEN — round-15 measured)
// ============================================================
#define G2_PAD   136
#define G2_A_E   (64 * G2_PAD)
#define G2_B_E   (128 * G2_PAD)
#define G2_SMEM  ((G2_A_E + G2_B_E) * 2)

__global__ __launch_bounds__(256, 3) void gemm2_mma(
    const float* __restrict__ AW, const float* __restrict__ XQ,
    float* __restrict__ OUT) {
    extern __shared__ __half sm2[];
    __half* Ah = sm2;
    const int t = threadIdx.x, lane = t & 31, wid = t >> 5;
    const int wm = wid >> 2, wn = wid & 3;
    const int b = blockIdx.x, mt = blockIdx.y, nt = blockIdx.z;
    const uint32_t sb = smem_u32(sm2);

    // B: cp.async v tile [k=128][n=128] (natural layout)
    {
        const __half* sh = g_vh + (size_t)b * KA * N_ + nt * 128;
        const uint32_t bh0 = sb + G2_A_E * 2;
        #pragma unroll
        for (int i = 0; i < 8; i++) {
            int idx = t + 256 * i;                 // 0..2047
            int row = idx >> 4, ch = (idx & 15) << 3;
            CP_ASYNC16(bh0 + (uint32_t)(row * G2_PAD + ch) * 2,
                       sh + (size_t)row * N_ + ch);
        }
        CP_COMMIT();
    }
    // A: convert aw (fp32, post-mask) to fp16 (overlaps B cp.async)
    {
        const float* asrc = AW + ((size_t)(b * C_ + mt * 64)) * KA;
        #pragma unroll
        for (int i = 0; i < 8; i++) {
            int idx = t + 256 * i;                 // 0..2047
            int row = idx >> 5, c4 = (idx & 31) << 2;
            float4 v = *reinterpret_cast<const float4*>(asrc + (size_t)row * KA + c4);
            __half* dh = Ah + row * G2_PAD + c4;
            dh[0] = __float2half_rn(v.x);
            dh[1] = __float2half_rn(v.y);
            dh[2] = __float2half_rn(v.z);
            dh[3] = __float2half_rn(v.w);
        }
    }
    CP_WAIT0();
    __syncthreads();

    float acc[2][4][4];
    #pragma unroll
    for (int i = 0; i < 2; i++)
        #pragma unroll
        for (int j = 0; j < 4; j++)
            #pragma unroll
            for (int e = 0; e < 4; e++) acc[i][j][e] = 0.f;

    const uint32_t oAh = 0;
    const uint32_t oBh = G2_A_E * 2;
    const int ar = lane & 15, axc = (lane >> 4) << 3;

    #pragma unroll
    for (int kk = 0; kk < 8; kk++) {
        const int k0 = kk * 16;
        uint32_t ah[2][4], bh[2][4];
        #pragma unroll
        for (int fm = 0; fm < 2; fm++) {
            uint32_t off = (uint32_t)((wm * 32 + fm * 16 + ar) * G2_PAD + k0 + axc) * 2;
            ldsm_x4(ah[fm], sb + oAh + off);
        }
        #pragma unroll
        for (int g = 0; g < 2; g++) {
            uint32_t off = (uint32_t)((k0 + ar) * G2_PAD + wn * 32 + g * 16 + axc) * 2;
            ldsm_x4_t(bh[g], sb + oBh + off);
        }
        #pragma unroll
        for (int fm = 0; fm < 2; fm++)
            #pragma unroll
            for (int fn = 0; fn < 4; fn++) {
                const int g = fn >> 1, p = (fn & 1) * 2;
                mma16816(acc[fm][fn], ah[fm], bh[g][p], bh[g][p + 1]);
            }
    }

    #pragma unroll
    for (int fm = 0; fm < 2; fm++) {
        int r0 = mt * 64 + wm * 32 + fm * 16 + (lane >> 2);
        #pragma unroll
        for (int fn = 0; fn < 4; fn++) {
            int cc = nt * 128 + wn * 32 + fn * 8 + (lane & 3) * 2;
            size_t off0 = ((size_t)(b * C_ + r0)) * N_ + cc;
            float2 x0 = *reinterpret_cast<const float2*>(XQ + off0);
            float2 o0 = make_float2(x0.x + acc[fm][fn][0], x0.y + acc[fm][fn][1]);
            *reinterpret_cast<float2*>(OUT + off0) = o0;
            size_t off1 = off0 + (size_t)8 * N_;
            float2 x1 = *reinterpret_cast<const float2*>(XQ + off1);
            float2 o1 = make_float2(x1.x + acc[fm][fn][2], x1.y + acc[fm][fn][3]);
            *reinterpret_cast<float2*>(OUT + off1) = o1;
        }
    }
}

// ============================================================
extern "C" void kernel_launch(void* const* d_in, const int* in_sizes, int n_in,
                              void* d_out, int out_size) {
    const float* x_q  = (const float*)d_in[0];
    const float* x_kv = (const float*)d_in[1];
    const float* wq   = (const float*)d_in[2];
    const float* bq   = (const float*)d_in[3];
    const float* wk   = (const float*)d_in[4];
    const float* bk   = (const float*)d_in[5];
    const float* wv   = (const float*)d_in[6];
    const float* bv   = (const float*)d_in[7];

    float* out1 = (float*)d_out;                   // [B,C,H,W]
    float* aw   = out1 + (size_t)B_ * C_ * N_;     // [B,C,K]

    static int configured = 0;
    if (!configured) {
        cudaFuncSetAttribute(gemm1_mma,
                             cudaFuncAttributeMaxDynamicSharedMemorySize, G1_SMEM);
        cudaFuncSetAttribute(gemm2_mma,
                             cudaFuncAttributeMaxDynamicSharedMemorySize, G2_SMEM);
        configured = 1;
    }

    dwconv_all_kernel    <<<B_ * C_ + B_ * KA, 256>>>(x_q, x_kv, wq, bq, wk, bk, wv, bv);
    gemm1_mma            <<<dim3(B_, 8, 8), 128, G1_SMEM>>>();
    reduce_softmax_kernel<<<B_ * C_ / 8, 256>>>(aw);
    topk_mask_kernel     <<<B_ * 16, 256>>>(aw);
    gemm2_mma            <<<dim3(B_, 8, 32), 256, G2_SMEM>>>(aw, x_q, out1);
}